// round 12
// baseline (speedup 1.0000x reference)
#include <cuda_runtime.h>
#include <cuda_fp16.h>
#include <cstdint>

// y = x @ W^T,  W[o,k] = scales[o,k/32] * (codes[o,k] - 128)
// R12: Stream-K persistent GEMM. 65536 k-iterations (1024 tiles x 64)
// split evenly over 304 persistent CTAs; cp.async pipeline continuous
// across tile boundaries; boundary tiles produce head/tail partials
// combined by a small kernel. Mainloop = R8/R11 (double-buffered
// ldmatrix frags, 3-stage, CTA 128x128, 4 warps of 64x64, 2 CTA/SM).

#define IN_DIM   4096
#define OUT_DIM  4096
#define M_DIM    4096
#define NBLK_    128

#define BM       128
#define BN       128
#define BK       64
#define STAGES   3
#define THREADS  128
#define KITERS   (IN_DIM / BK)     // 64

#define NTILES    1024
#define TOT_ITERS (NTILES * KITERS)   // 65536
#define GRID_P    304                  // 152 SMs x 2 CTA/SM
#define BASEC     (TOT_ITERS / GRID_P) // 215
#define EXTRA     (TOT_ITERS - GRID_P * BASEC) // 176

__device__ __half g_xh[(size_t)M_DIM * IN_DIM];
__device__ __half g_wh[(size_t)OUT_DIM * IN_DIM];
__device__ float  g_head[(size_t)GRID_P * BM * BN];   // 19.9 MB
__device__ float  g_tail[(size_t)GRID_P * BM * BN];

#define A_STAGE_H   (BM * BK)
#define B_STAGE_H   (BN * BK)
#define B_BASE_H    (STAGES * A_STAGE_H)
#define SMEM_BYTES  ((STAGES * (A_STAGE_H + B_STAGE_H)) * 2)   // 98304

// ---------------- prepass (R11, MLP=4) ----------------
#define NX4 ((M_DIM * IN_DIM) / 4)
#define NW4 ((OUT_DIM * IN_DIM) / 4)
#define PRE_T    256
#define PRE_C    4
#define PRE_XBLK (NX4 / (PRE_T * PRE_C))
#define PRE_WBLK (NW4 / (PRE_T * PRE_C))

__global__ void prepass_kernel(const float4* __restrict__ x,
                               const float* __restrict__ scales,
                               const int4* __restrict__ codes) {
    int b = blockIdx.x;
    if (b < PRE_XBLK) {
        int base = b * (PRE_T * PRE_C) + threadIdx.x;
        float4 v[PRE_C];
        #pragma unroll
        for (int j = 0; j < PRE_C; j++) v[j] = x[base + j * PRE_T];
        #pragma unroll
        for (int j = 0; j < PRE_C; j++) {
            __half2 h0 = __floats2half2_rn(v[j].x, v[j].y);
            __half2 h1 = __floats2half2_rn(v[j].z, v[j].w);
            uint2 u;
            u.x = *reinterpret_cast<uint32_t*>(&h0);
            u.y = *reinterpret_cast<uint32_t*>(&h1);
            reinterpret_cast<uint2*>(g_xh)[base + j * PRE_T] = u;
        }
    } else {
        int base = (b - PRE_XBLK) * (PRE_T * PRE_C) + threadIdx.x;
        int4 c[PRE_C];
        float s[PRE_C];
        #pragma unroll
        for (int j = 0; j < PRE_C; j++) {
            int idx = base + j * PRE_T;
            c[j] = codes[idx];
            int gelt = idx * 4;
            s[j] = __ldg(scales + (gelt >> 12) * NBLK_ + ((gelt & 4095) >> 5));
        }
        #pragma unroll
        for (int j = 0; j < PRE_C; j++) {
            __half2 h0 = __floats2half2_rn(s[j] * (float)(c[j].x - 128),
                                           s[j] * (float)(c[j].y - 128));
            __half2 h1 = __floats2half2_rn(s[j] * (float)(c[j].z - 128),
                                           s[j] * (float)(c[j].w - 128));
            uint2 u;
            u.x = *reinterpret_cast<uint32_t*>(&h0);
            u.y = *reinterpret_cast<uint32_t*>(&h1);
            reinterpret_cast<uint2*>(g_wh)[base + j * PRE_T] = u;
        }
    }
}

// ---------------- GEMM helpers ----------------

__device__ __forceinline__ void cp_async16(uint32_t saddr, const void* g) {
    asm volatile("cp.async.cg.shared.global [%0], [%1], 16;" :: "r"(saddr), "l"(g));
}
__device__ __forceinline__ void cp_commit() {
    asm volatile("cp.async.commit_group;");
}
template <int N>
__device__ __forceinline__ void cp_wait() {
    asm volatile("cp.async.wait_group %0;" :: "n"(N));
}
__device__ __forceinline__ void ldsm_x4(uint32_t& r0, uint32_t& r1,
                                        uint32_t& r2, uint32_t& r3, uint32_t addr) {
    asm volatile("ldmatrix.sync.aligned.m8n8.x4.shared.b16 {%0,%1,%2,%3}, [%4];"
                 : "=r"(r0), "=r"(r1), "=r"(r2), "=r"(r3) : "r"(addr));
}
__device__ __forceinline__ void mma_f16(float* c, const uint32_t* a, const uint32_t* b) {
    asm volatile(
        "mma.sync.aligned.m16n8k16.row.col.f32.f16.f16.f32 "
        "{%0,%1,%2,%3}, {%4,%5,%6,%7}, {%8,%9}, {%0,%1,%2,%3};"
        : "+f"(c[0]), "+f"(c[1]), "+f"(c[2]), "+f"(c[3])
        : "r"(a[0]), "r"(a[1]), "r"(a[2]), "r"(a[3]), "r"(b[0]), "r"(b[1]));
}

__device__ __forceinline__ int tile_off(int row, int chunk) {
    return row * BK + ((chunk ^ (row & 7)) << 3);
}

// load stage for global iteration g into slot st
__device__ __forceinline__ void load_stage_g(int g, int st, int tid, uint32_t smem_u32) {
    int t  = g >> 6;
    int kb = g & 63;
    int m0 = (t >> 5) * BM;
    int n0 = (t & 31) * BN;
    const __half* gA = g_xh + (size_t)m0 * IN_DIM + kb * BK;
    const __half* gB = g_wh + (size_t)n0 * IN_DIM + kb * BK;
    uint32_t aBase = smem_u32 + (uint32_t)(st * A_STAGE_H) * 2;
    uint32_t bBase = smem_u32 + (uint32_t)(B_BASE_H + st * B_STAGE_H) * 2;
    #pragma unroll
    for (int it = 0; it < 8; it++) {
        int idx = tid + it * THREADS;
        int row = idx >> 3, ch = idx & 7;
        cp_async16(aBase + (uint32_t)tile_off(row, ch) * 2,
                   gA + (size_t)row * IN_DIM + ch * 8);
    }
    #pragma unroll
    for (int it = 0; it < 8; it++) {
        int idx = tid + it * THREADS;
        int row = idx >> 3, ch = idx & 7;
        cp_async16(bBase + (uint32_t)tile_off(row, ch) * 2,
                   gB + (size_t)row * IN_DIM + ch * 8);
    }
}

struct Frag {
    uint32_t a[4][4];
    uint32_t b[8][2];
};

__global__ __launch_bounds__(THREADS, 2)
void gguf_hgemm10(float* __restrict__ y) {
    extern __shared__ __half sm[];
    uint32_t smem_u32 = (uint32_t)__cvta_generic_to_shared(sm);

    const int tid  = threadIdx.x;
    const int lane = tid & 31;
    const int wid  = tid >> 5;
    const int wm   = wid >> 1;
    const int wn   = wid & 1;

    const int c   = blockIdx.x;
    const int s_c = c * BASEC + (c < EXTRA ? c : EXTRA);
    const int e_c = s_c + BASEC + (c < EXTRA ? 1 : 0);

    float acc[4][8][4];
    #pragma unroll
    for (int i = 0; i < 4; i++)
        #pragma unroll
        for (int j = 0; j < 8; j++)
            #pragma unroll
            for (int v = 0; v < 4; v++) acc[i][j][v] = 0.0f;

    const int a_lr = lane & 15;
    const int a_lc = lane >> 4;
    const int b_lr = (lane & 7) + ((lane >> 4) << 3);
    const int b_lc = (lane >> 3) & 1;

    int rowA[4], rowB[4];
    #pragma unroll
    for (int mt = 0; mt < 4; mt++) rowA[mt] = wm * 64 + mt * 16 + a_lr;
    #pragma unroll
    for (int p = 0; p < 4; p++)    rowB[p]  = wn * 64 + p * 16 + b_lr;

    auto load_frags = [&](Frag& f, uint32_t aBase, uint32_t bBase, int ks) {
        const int ck0 = ks * 2;
        #pragma unroll
        for (int mt = 0; mt < 4; mt++) {
            int r = rowA[mt];
            uint32_t addr = aBase +
                (uint32_t)(r * BK + (((ck0 + a_lc) ^ (r & 7)) << 3)) * 2;
            ldsm_x4(f.a[mt][0], f.a[mt][1], f.a[mt][2], f.a[mt][3], addr);
        }
        #pragma unroll
        for (int p = 0; p < 4; p++) {
            int r = rowB[p];
            uint32_t addr = bBase +
                (uint32_t)(r * BK + (((ck0 + b_lc) ^ (r & 7)) << 3)) * 2;
            uint32_t r0, r1, r2, r3;
            ldsm_x4(r0, r1, r2, r3, addr);
            f.b[2 * p][0] = r0;     f.b[2 * p][1] = r1;
            f.b[2 * p + 1][0] = r2; f.b[2 * p + 1][1] = r3;
        }
    };

    auto stage_a = [&](int s) {
        return smem_u32 + (uint32_t)(s * A_STAGE_H) * 2;
    };
    auto stage_b = [&](int s) {
        return smem_u32 + (uint32_t)(B_BASE_H + s * B_STAGE_H) * 2;
    };

    // prologue (chunk length >= 215, so s_c+1 < e_c always)
    load_stage_g(s_c,     0, tid, smem_u32); cp_commit();
    load_stage_g(s_c + 1, 1, tid, smem_u32); cp_commit();
    cp_wait<1>();
    __syncthreads();

    Frag frag[2];
    load_frags(frag[0], stage_a(0), stage_b(0), 0);
    int fb = 0;

    const int lrow_q = lane >> 2;
    const int lcol_q = lane & 3;

    int s = 0;
    for (int g = s_c; g < e_c; g++) {
        const uint32_t aB = stage_a(s);
        const uint32_t bB = stage_b(s);
        const int sn = (s + 1 == STAGES) ? 0 : s + 1;

        #pragma unroll
        for (int ks = 0; ks < BK / 16; ks++) {
            const int nb = fb ^ 1;
            if (ks < BK / 16 - 1) {
                load_frags(frag[nb], aB, bB, ks + 1);
            } else {
                if (g + 2 < e_c) {
                    int s2 = (s + 2 >= STAGES) ? s + 2 - STAGES : s + 2;
                    load_stage_g(g + 2, s2, tid, smem_u32);
                }
                cp_commit();
                cp_wait<1>();
                __syncthreads();
                if (g + 1 < e_c)
                    load_frags(frag[nb], stage_a(sn), stage_b(sn), 0);
            }
            #pragma unroll
            for (int mt = 0; mt < 4; mt++)
                #pragma unroll
                for (int nt = 0; nt < 8; nt++)
                    mma_f16(acc[mt][nt], frag[fb].a[mt], frag[fb].b[nt]);
            fb = nb;
        }
        s = sn;

        // piece boundary?
        const int kb = g & 63;
        if (kb == 63 || g + 1 == e_c) {
            const int t = g >> 6;
            const int tstart = t << 6;
            const bool fullt = (tstart >= s_c) && (tstart + KITERS <= e_c);
            float* dst;
            int dstride;
            if (fullt) {
                dst = y + (size_t)((t >> 5) * BM) * OUT_DIM + (t & 31) * BN;
                dstride = OUT_DIM;
            } else if (tstart < s_c) {                 // head piece of this chunk
                dst = g_head + (size_t)c * (BM * BN);
                dstride = BN;
            } else {                                   // tail piece
                dst = g_tail + (size_t)c * (BM * BN);
                dstride = BN;
            }
            const int mrow  = wm * 64 + lrow_q;
            const int ncol0 = wn * 64 + lcol_q * 2;
            #pragma unroll
            for (int mt = 0; mt < 4; mt++) {
                #pragma unroll
                for (int nt = 0; nt < 8; nt++) {
                    int r = mrow + mt * 16;
                    int cc = ncol0 + nt * 8;
                    float2 lo = make_float2(acc[mt][nt][0], acc[mt][nt][1]);
                    float2 hi = make_float2(acc[mt][nt][2], acc[mt][nt][3]);
                    if (fullt) {
                        __stcs(reinterpret_cast<float2*>(dst + (size_t)r * dstride + cc), lo);
                        __stcs(reinterpret_cast<float2*>(dst + (size_t)(r + 8) * dstride + cc), hi);
                    } else {
                        *reinterpret_cast<float2*>(dst + (size_t)r * dstride + cc) = lo;
                        *reinterpret_cast<float2*>(dst + (size_t)(r + 8) * dstride + cc) = hi;
                    }
                    acc[mt][nt][0] = 0.0f; acc[mt][nt][1] = 0.0f;
                    acc[mt][nt][2] = 0.0f; acc[mt][nt][3] = 0.0f;
                }
            }
        }
    }
}

// ---------------- combine split tiles ----------------
// boundary c (1..303): if s_c % 64 != 0, tile s_c/64 = tail[c-1] + head[c]
#define COMB_V4 ((GRID_P - 1) * (BM * BN / 4))

__global__ void combine_kernel(float* __restrict__ y) {
    int j = blockIdx.x * blockDim.x + threadIdx.x;
    if (j >= COMB_V4) return;
    int c  = 1 + (j >> 12);          // / 4096
    int e4 = j & 4095;
    int s_c = c * BASEC + (c < EXTRA ? c : EXTRA);
    if ((s_c & 63) == 0) return;     // no split at this boundary
    int t = s_c >> 6;
    float4 a = reinterpret_cast<const float4*>(g_tail + (size_t)(c - 1) * (BM * BN))[e4];
    float4 b = reinterpret_cast<const float4*>(g_head + (size_t)c * (BM * BN))[e4];
    a.x += b.x; a.y += b.y; a.z += b.z; a.w += b.w;
    int e = e4 * 4;
    int r = e >> 7;
    int col = e & 127;
    *reinterpret_cast<float4*>(
        y + (size_t)((t >> 5) * BM + r) * OUT_DIM + (t & 31) * BN + col) = a;
}

extern "C" void kernel_launch(void* const* d_in, const int* in_sizes, int n_in,
                              void* d_out, int out_size) {
    const float* x      = (const float*)d_in[0];
    const float* scales = (const float*)d_in[1];
    const int*   codes  = (const int*)d_in[2];
    float*       y      = (float*)d_out;

    cudaFuncSetAttribute(gguf_hgemm10, cudaFuncAttributeMaxDynamicSharedMemorySize,
                         SMEM_BYTES);

    prepass_kernel<<<PRE_XBLK + PRE_WBLK, PRE_T>>>(
        reinterpret_cast<const float4*>(x), scales,
        reinterpret_cast<const int4*>(codes));

    gguf_hgemm10<<<GRID_P, THREADS, SMEM_BYTES>>>(y);

    combine_kernel<<<(COMB_V4 + 255) / 256, 256>>>(y);
}

// round 13
// speedup vs baseline: 1.0087x; 1.0087x over previous
#include <cuda_runtime.h>
#include <cuda_fp16.h>
#include <cstdint>

// y = x @ W^T,  W[o,k] = scales[o,k/32] * (codes[o,k] - 128)
// R13: R11 GEMM (CTA 128x128, 4 warps of 64x64, 3-stage cp.async,
// double-buffered ldmatrix frags, 2 CTA/SM, streaming epilogue) with the
// stage-boundary pipeline ops moved one ks earlier (barrier at ks2,
// covered by ks2+ks3 MMA batches) + MLP=8 prepass. Stream-K reverted.

#define IN_DIM   4096
#define OUT_DIM  4096
#define M_DIM    4096
#define NBLK_    128

#define BM       128
#define BN       128
#define BK       64
#define STAGES   3
#define THREADS  128
#define KITERS   (IN_DIM / BK)   // 64

__device__ __half g_xh[(size_t)M_DIM * IN_DIM];
__device__ __half g_wh[(size_t)OUT_DIM * IN_DIM];

#define A_STAGE_H   (BM * BK)                     // 8192 halves (16 KB)
#define B_STAGE_H   (BN * BK)
#define B_BASE_H    (STAGES * A_STAGE_H)
#define SMEM_BYTES  ((STAGES * (A_STAGE_H + B_STAGE_H)) * 2)   // 98304

// ---------------- prepass: MLP=8 ----------------
#define NX4 ((M_DIM * IN_DIM) / 4)
#define NW4 ((OUT_DIM * IN_DIM) / 4)
#define PRE_T    256
#define PRE_C    8
#define PRE_XBLK (NX4 / (PRE_T * PRE_C))   // 2048
#define PRE_WBLK (NW4 / (PRE_T * PRE_C))   // 2048

__global__ void prepass_kernel(const float4* __restrict__ x,
                               const float* __restrict__ scales,
                               const int4* __restrict__ codes) {
    int b = blockIdx.x;
    if (b < PRE_XBLK) {
        int base = b * (PRE_T * PRE_C) + threadIdx.x;
        float4 v[PRE_C];
        #pragma unroll
        for (int j = 0; j < PRE_C; j++) v[j] = x[base + j * PRE_T];
        #pragma unroll
        for (int j = 0; j < PRE_C; j++) {
            __half2 h0 = __floats2half2_rn(v[j].x, v[j].y);
            __half2 h1 = __floats2half2_rn(v[j].z, v[j].w);
            uint2 u;
            u.x = *reinterpret_cast<uint32_t*>(&h0);
            u.y = *reinterpret_cast<uint32_t*>(&h1);
            reinterpret_cast<uint2*>(g_xh)[base + j * PRE_T] = u;
        }
    } else {
        int base = (b - PRE_XBLK) * (PRE_T * PRE_C) + threadIdx.x;
        int4 c[PRE_C];
        float s[PRE_C];
        #pragma unroll
        for (int j = 0; j < PRE_C; j++) {
            int idx = base + j * PRE_T;
            c[j] = codes[idx];
            int gelt = idx * 4;
            s[j] = __ldg(scales + (gelt >> 12) * NBLK_ + ((gelt & 4095) >> 5));
        }
        #pragma unroll
        for (int j = 0; j < PRE_C; j++) {
            __half2 h0 = __floats2half2_rn(s[j] * (float)(c[j].x - 128),
                                           s[j] * (float)(c[j].y - 128));
            __half2 h1 = __floats2half2_rn(s[j] * (float)(c[j].z - 128),
                                           s[j] * (float)(c[j].w - 128));
            uint2 u;
            u.x = *reinterpret_cast<uint32_t*>(&h0);
            u.y = *reinterpret_cast<uint32_t*>(&h1);
            reinterpret_cast<uint2*>(g_wh)[base + j * PRE_T] = u;
        }
    }
}

// ---------------- GEMM helpers ----------------

__device__ __forceinline__ void cp_async16(uint32_t saddr, const void* g) {
    asm volatile("cp.async.cg.shared.global [%0], [%1], 16;" :: "r"(saddr), "l"(g));
}
__device__ __forceinline__ void cp_commit() {
    asm volatile("cp.async.commit_group;");
}
template <int N>
__device__ __forceinline__ void cp_wait() {
    asm volatile("cp.async.wait_group %0;" :: "n"(N));
}
__device__ __forceinline__ void ldsm_x4(uint32_t& r0, uint32_t& r1,
                                        uint32_t& r2, uint32_t& r3, uint32_t addr) {
    asm volatile("ldmatrix.sync.aligned.m8n8.x4.shared.b16 {%0,%1,%2,%3}, [%4];"
                 : "=r"(r0), "=r"(r1), "=r"(r2), "=r"(r3) : "r"(addr));
}
__device__ __forceinline__ void mma_f16(float* c, const uint32_t* a, const uint32_t* b) {
    asm volatile(
        "mma.sync.aligned.m16n8k16.row.col.f32.f16.f16.f32 "
        "{%0,%1,%2,%3}, {%4,%5,%6,%7}, {%8,%9}, {%0,%1,%2,%3};"
        : "+f"(c[0]), "+f"(c[1]), "+f"(c[2]), "+f"(c[3])
        : "r"(a[0]), "r"(a[1]), "r"(a[2]), "r"(a[3]), "r"(b[0]), "r"(b[1]));
}

__device__ __forceinline__ int tile_off(int row, int chunk) {
    return row * BK + ((chunk ^ (row & 7)) << 3);
}

__device__ __forceinline__ void load_stage(int kb, int st, int m0, int n0,
                                           int tid, uint32_t smem_u32) {
    const __half* gA = g_xh + (size_t)m0 * IN_DIM + kb * BK;
    const __half* gB = g_wh + (size_t)n0 * IN_DIM + kb * BK;
    uint32_t aBase = smem_u32 + (uint32_t)(st * A_STAGE_H) * 2;
    uint32_t bBase = smem_u32 + (uint32_t)(B_BASE_H + st * B_STAGE_H) * 2;
    #pragma unroll
    for (int it = 0; it < 8; it++) {
        int idx = tid + it * THREADS;
        int row = idx >> 3, ch = idx & 7;
        cp_async16(aBase + (uint32_t)tile_off(row, ch) * 2,
                   gA + (size_t)row * IN_DIM + ch * 8);
    }
    #pragma unroll
    for (int it = 0; it < 8; it++) {
        int idx = tid + it * THREADS;
        int row = idx >> 3, ch = idx & 7;
        cp_async16(bBase + (uint32_t)tile_off(row, ch) * 2,
                   gB + (size_t)row * IN_DIM + ch * 8);
    }
}

struct Frag {
    uint32_t a[4][4];
    uint32_t b[8][2];
};

__global__ __launch_bounds__(THREADS, 2)
void gguf_hgemm11(float* __restrict__ y) {
    extern __shared__ __half sm[];
    uint32_t smem_u32 = (uint32_t)__cvta_generic_to_shared(sm);

    const int tid  = threadIdx.x;
    const int lane = tid & 31;
    const int wid  = tid >> 5;
    const int wm   = wid >> 1;     // 0..1 -> 64 m rows
    const int wn   = wid & 1;      // 0..1 -> 64 n cols

    const int m0 = blockIdx.y * BM;
    const int n0 = blockIdx.x * BN;

    float acc[4][8][4];
    #pragma unroll
    for (int i = 0; i < 4; i++)
        #pragma unroll
        for (int j = 0; j < 8; j++)
            #pragma unroll
            for (int v = 0; v < 4; v++) acc[i][j][v] = 0.0f;

    const int a_lr = lane & 15;
    const int a_lc = lane >> 4;
    const int b_lr = (lane & 7) + ((lane >> 4) << 3);
    const int b_lc = (lane >> 3) & 1;

    int rowA[4], rowB[4];
    #pragma unroll
    for (int mt = 0; mt < 4; mt++) rowA[mt] = wm * 64 + mt * 16 + a_lr;
    #pragma unroll
    for (int p = 0; p < 4; p++)    rowB[p]  = wn * 64 + p * 16 + b_lr;

    auto load_frags = [&](Frag& f, uint32_t aBase, uint32_t bBase, int ks) {
        const int ck0 = ks * 2;
        #pragma unroll
        for (int mt = 0; mt < 4; mt++) {
            int r = rowA[mt];
            uint32_t addr = aBase +
                (uint32_t)(r * BK + (((ck0 + a_lc) ^ (r & 7)) << 3)) * 2;
            ldsm_x4(f.a[mt][0], f.a[mt][1], f.a[mt][2], f.a[mt][3], addr);
        }
        #pragma unroll
        for (int p = 0; p < 4; p++) {
            int r = rowB[p];
            uint32_t addr = bBase +
                (uint32_t)(r * BK + (((ck0 + b_lc) ^ (r & 7)) << 3)) * 2;
            uint32_t r0, r1, r2, r3;
            ldsm_x4(r0, r1, r2, r3, addr);
            f.b[2 * p][0] = r0;     f.b[2 * p][1] = r1;
            f.b[2 * p + 1][0] = r2; f.b[2 * p + 1][1] = r3;
        }
    };

    auto stage_a = [&](int s) {
        return smem_u32 + (uint32_t)(s * A_STAGE_H) * 2;
    };
    auto stage_b = [&](int s) {
        return smem_u32 + (uint32_t)(B_BASE_H + s * B_STAGE_H) * 2;
    };

    // prologue
    load_stage(0, 0, m0, n0, tid, smem_u32); cp_commit();
    load_stage(1, 1, m0, n0, tid, smem_u32); cp_commit();
    cp_wait<1>();
    __syncthreads();

    Frag frag[2];
    load_frags(frag[0], stage_a(0), stage_b(0), 0);
    int fb = 0;

    int s = 0;
    for (int kb = 0; kb < KITERS; kb++) {
        const uint32_t aB = stage_a(s);
        const uint32_t bB = stage_b(s);
        const int sn = (s + 1 == STAGES) ? 0 : s + 1;

        #pragma unroll
        for (int ks = 0; ks < BK / 16; ks++) {
            const int nb = fb ^ 1;
            if (ks < BK / 16 - 2) {
                // ks 0,1: prefetch frags for ks+1
                load_frags(frag[nb], aB, bB, ks + 1);
            } else if (ks == BK / 16 - 2) {
                // ks2: prefetch ks3 frags, then stage pipeline ops + barrier.
                // ks2+ks3 MMA batches (~64 MMAs) cover barrier release and
                // the next-stage LDSM latency.
                load_frags(frag[nb], aB, bB, ks + 1);
                int nk = kb + 2;
                if (nk < KITERS) {
                    int s2 = (s + 2 >= STAGES) ? s + 2 - STAGES : s + 2;
                    load_stage(nk, s2, m0, n0, tid, smem_u32);
                }
                cp_commit();
                cp_wait<1>();          // stage kb+1 resident
                __syncthreads();
            } else {
                // ks3: frags for next stage ks0 (data guaranteed by ks2 wait)
                if (kb + 1 < KITERS)
                    load_frags(frag[nb], stage_a(sn), stage_b(sn), 0);
            }
            #pragma unroll
            for (int mt = 0; mt < 4; mt++)
                #pragma unroll
                for (int nt = 0; nt < 8; nt++)
                    mma_f16(acc[mt][nt], frag[fb].a[mt], frag[fb].b[nt]);
            fb = nb;
        }

        s = sn;
    }

    // epilogue: streaming stores
    const int lrow_q = lane >> 2;
    const int lcol_q = lane & 3;
    const int mrow  = m0 + wm * 64 + lrow_q;
    const int ncol0 = n0 + wn * 64 + lcol_q * 2;
    #pragma unroll
    for (int mt = 0; mt < 4; mt++) {
        #pragma unroll
        for (int nt = 0; nt < 8; nt++) {
            int r = mrow + mt * 16;
            int c = ncol0 + nt * 8;
            float2 lo = make_float2(acc[mt][nt][0], acc[mt][nt][1]);
            float2 hi = make_float2(acc[mt][nt][2], acc[mt][nt][3]);
            __stcs(reinterpret_cast<float2*>(y + (size_t)r * OUT_DIM + c), lo);
            __stcs(reinterpret_cast<float2*>(y + (size_t)(r + 8) * OUT_DIM + c), hi);
        }
    }
}

extern "C" void kernel_launch(void* const* d_in, const int* in_sizes, int n_in,
                              void* d_out, int out_size) {
    const float* x      = (const float*)d_in[0];
    const float* scales = (const float*)d_in[1];
    const int*   codes  = (const int*)d_in[2];
    float*       y      = (float*)d_out;

    cudaFuncSetAttribute(gguf_hgemm11, cudaFuncAttributeMaxDynamicSharedMemorySize,
                         SMEM_BYTES);

    prepass_kernel<<<PRE_XBLK + PRE_WBLK, PRE_T>>>(
        reinterpret_cast<const float4*>(x), scales,
        reinterpret_cast<const int4*>(codes));

    dim3 grid(OUT_DIM / BN, M_DIM / BM);   // (32, 32)
    gguf_hgemm11<<<grid, THREADS, SMEM_BYTES>>>(y);
}

// round 14
// speedup vs baseline: 1.0166x; 1.0078x over previous
#include <cuda_runtime.h>
#include <cuda_fp16.h>
#include <cstdint>

// y = x @ W^T,  W[o,k] = scales[o,k/32] * (codes[o,k] - 128)
// R14: R11/R13 GEMM (CTA 128x128, 4 warps of 64x64, 3-stage cp.async,
// double-buffered ldmatrix frags, 2 CTA/SM, streaming epilogue) with the
// stage fill split across ks: A-half at ks0, B-half at ks1, commit+wait+
// barrier at ks2, next-stage frags at ks3. Prepass = MLP=4 (measured best).

#define IN_DIM   4096
#define OUT_DIM  4096
#define M_DIM    4096
#define NBLK_    128

#define BM       128
#define BN       128
#define BK       64
#define STAGES   3
#define THREADS  128
#define KITERS   (IN_DIM / BK)   // 64

__device__ __half g_xh[(size_t)M_DIM * IN_DIM];
__device__ __half g_wh[(size_t)OUT_DIM * IN_DIM];

#define A_STAGE_H   (BM * BK)                     // 8192 halves (16 KB)
#define B_STAGE_H   (BN * BK)
#define B_BASE_H    (STAGES * A_STAGE_H)
#define SMEM_BYTES  ((STAGES * (A_STAGE_H + B_STAGE_H)) * 2)   // 98304

// ---------------- prepass: MLP=4 ----------------
#define NX4 ((M_DIM * IN_DIM) / 4)
#define NW4 ((OUT_DIM * IN_DIM) / 4)
#define PRE_T    256
#define PRE_C    4
#define PRE_XBLK (NX4 / (PRE_T * PRE_C))  // 4096
#define PRE_WBLK (NW4 / (PRE_T * PRE_C))  // 4096

__global__ void prepass_kernel(const float4* __restrict__ x,
                               const float* __restrict__ scales,
                               const int4* __restrict__ codes) {
    int b = blockIdx.x;
    if (b < PRE_XBLK) {
        int base = b * (PRE_T * PRE_C) + threadIdx.x;
        float4 v[PRE_C];
        #pragma unroll
        for (int j = 0; j < PRE_C; j++) v[j] = x[base + j * PRE_T];
        #pragma unroll
        for (int j = 0; j < PRE_C; j++) {
            __half2 h0 = __floats2half2_rn(v[j].x, v[j].y);
            __half2 h1 = __floats2half2_rn(v[j].z, v[j].w);
            uint2 u;
            u.x = *reinterpret_cast<uint32_t*>(&h0);
            u.y = *reinterpret_cast<uint32_t*>(&h1);
            reinterpret_cast<uint2*>(g_xh)[base + j * PRE_T] = u;
        }
    } else {
        int base = (b - PRE_XBLK) * (PRE_T * PRE_C) + threadIdx.x;
        int4 c[PRE_C];
        float s[PRE_C];
        #pragma unroll
        for (int j = 0; j < PRE_C; j++) {
            int idx = base + j * PRE_T;
            c[j] = codes[idx];
            int gelt = idx * 4;
            s[j] = __ldg(scales + (gelt >> 12) * NBLK_ + ((gelt & 4095) >> 5));
        }
        #pragma unroll
        for (int j = 0; j < PRE_C; j++) {
            __half2 h0 = __floats2half2_rn(s[j] * (float)(c[j].x - 128),
                                           s[j] * (float)(c[j].y - 128));
            __half2 h1 = __floats2half2_rn(s[j] * (float)(c[j].z - 128),
                                           s[j] * (float)(c[j].w - 128));
            uint2 u;
            u.x = *reinterpret_cast<uint32_t*>(&h0);
            u.y = *reinterpret_cast<uint32_t*>(&h1);
            reinterpret_cast<uint2*>(g_wh)[base + j * PRE_T] = u;
        }
    }
}

// ---------------- GEMM helpers ----------------

__device__ __forceinline__ void cp_async16(uint32_t saddr, const void* g) {
    asm volatile("cp.async.cg.shared.global [%0], [%1], 16;" :: "r"(saddr), "l"(g));
}
__device__ __forceinline__ void cp_commit() {
    asm volatile("cp.async.commit_group;");
}
template <int N>
__device__ __forceinline__ void cp_wait() {
    asm volatile("cp.async.wait_group %0;" :: "n"(N));
}
__device__ __forceinline__ void ldsm_x4(uint32_t& r0, uint32_t& r1,
                                        uint32_t& r2, uint32_t& r3, uint32_t addr) {
    asm volatile("ldmatrix.sync.aligned.m8n8.x4.shared.b16 {%0,%1,%2,%3}, [%4];"
                 : "=r"(r0), "=r"(r1), "=r"(r2), "=r"(r3) : "r"(addr));
}
__device__ __forceinline__ void mma_f16(float* c, const uint32_t* a, const uint32_t* b) {
    asm volatile(
        "mma.sync.aligned.m16n8k16.row.col.f32.f16.f16.f32 "
        "{%0,%1,%2,%3}, {%4,%5,%6,%7}, {%8,%9}, {%0,%1,%2,%3};"
        : "+f"(c[0]), "+f"(c[1]), "+f"(c[2]), "+f"(c[3])
        : "r"(a[0]), "r"(a[1]), "r"(a[2]), "r"(a[3]), "r"(b[0]), "r"(b[1]));
}

__device__ __forceinline__ int tile_off(int row, int chunk) {
    return row * BK + ((chunk ^ (row & 7)) << 3);
}

__device__ __forceinline__ void load_stage_A(int kb, int st, int m0,
                                             int tid, uint32_t smem_u32) {
    const __half* gA = g_xh + (size_t)m0 * IN_DIM + kb * BK;
    uint32_t aBase = smem_u32 + (uint32_t)(st * A_STAGE_H) * 2;
    #pragma unroll
    for (int it = 0; it < 8; it++) {
        int idx = tid + it * THREADS;
        int row = idx >> 3, ch = idx & 7;
        cp_async16(aBase + (uint32_t)tile_off(row, ch) * 2,
                   gA + (size_t)row * IN_DIM + ch * 8);
    }
}
__device__ __forceinline__ void load_stage_B(int kb, int st, int n0,
                                             int tid, uint32_t smem_u32) {
    const __half* gB = g_wh + (size_t)n0 * IN_DIM + kb * BK;
    uint32_t bBase = smem_u32 + (uint32_t)(B_BASE_H + st * B_STAGE_H) * 2;
    #pragma unroll
    for (int it = 0; it < 8; it++) {
        int idx = tid + it * THREADS;
        int row = idx >> 3, ch = idx & 7;
        cp_async16(bBase + (uint32_t)tile_off(row, ch) * 2,
                   gB + (size_t)row * IN_DIM + ch * 8);
    }
}

struct Frag {
    uint32_t a[4][4];
    uint32_t b[8][2];
};

__global__ __launch_bounds__(THREADS, 2)
void gguf_hgemm12(float* __restrict__ y) {
    extern __shared__ __half sm[];
    uint32_t smem_u32 = (uint32_t)__cvta_generic_to_shared(sm);

    const int tid  = threadIdx.x;
    const int lane = tid & 31;
    const int wid  = tid >> 5;
    const int wm   = wid >> 1;     // 0..1 -> 64 m rows
    const int wn   = wid & 1;      // 0..1 -> 64 n cols

    const int m0 = blockIdx.y * BM;
    const int n0 = blockIdx.x * BN;

    float acc[4][8][4];
    #pragma unroll
    for (int i = 0; i < 4; i++)
        #pragma unroll
        for (int j = 0; j < 8; j++)
            #pragma unroll
            for (int v = 0; v < 4; v++) acc[i][j][v] = 0.0f;

    const int a_lr = lane & 15;
    const int a_lc = lane >> 4;
    const int b_lr = (lane & 7) + ((lane >> 4) << 3);
    const int b_lc = (lane >> 3) & 1;

    int rowA[4], rowB[4];
    #pragma unroll
    for (int mt = 0; mt < 4; mt++) rowA[mt] = wm * 64 + mt * 16 + a_lr;
    #pragma unroll
    for (int p = 0; p < 4; p++)    rowB[p]  = wn * 64 + p * 16 + b_lr;

    auto load_frags = [&](Frag& f, uint32_t aBase, uint32_t bBase, int ks) {
        const int ck0 = ks * 2;
        #pragma unroll
        for (int mt = 0; mt < 4; mt++) {
            int r = rowA[mt];
            uint32_t addr = aBase +
                (uint32_t)(r * BK + (((ck0 + a_lc) ^ (r & 7)) << 3)) * 2;
            ldsm_x4(f.a[mt][0], f.a[mt][1], f.a[mt][2], f.a[mt][3], addr);
        }
        #pragma unroll
        for (int p = 0; p < 4; p++) {
            int r = rowB[p];
            uint32_t addr = bBase +
                (uint32_t)(r * BK + (((ck0 + b_lc) ^ (r & 7)) << 3)) * 2;
            uint32_t r0, r1, r2, r3;
            ldsm_x4(r0, r1, r2, r3, addr);
            f.b[2 * p][0] = r0;     f.b[2 * p][1] = r1;
            f.b[2 * p + 1][0] = r2; f.b[2 * p + 1][1] = r3;
        }
    };

    auto stage_a = [&](int s) {
        return smem_u32 + (uint32_t)(s * A_STAGE_H) * 2;
    };
    auto stage_b = [&](int s) {
        return smem_u32 + (uint32_t)(B_BASE_H + s * B_STAGE_H) * 2;
    };

    // prologue
    load_stage_A(0, 0, m0, tid, smem_u32);
    load_stage_B(0, 0, n0, tid, smem_u32); cp_commit();
    load_stage_A(1, 1, m0, tid, smem_u32);
    load_stage_B(1, 1, n0, tid, smem_u32); cp_commit();
    cp_wait<1>();
    __syncthreads();

    Frag frag[2];
    load_frags(frag[0], stage_a(0), stage_b(0), 0);
    int fb = 0;

    int s = 0;
    for (int kb = 0; kb < KITERS; kb++) {
        const uint32_t aB = stage_a(s);
        const uint32_t bB = stage_b(s);
        const int sn = (s + 1 == STAGES) ? 0 : s + 1;
        const int nk = kb + 2;
        const int s2 = (s + 2 >= STAGES) ? s + 2 - STAGES : s + 2;

        #pragma unroll
        for (int ks = 0; ks < BK / 16; ks++) {
            const int nb = fb ^ 1;
            if (ks == 0) {
                // prefetch frags ks1; issue A-half of stage kb+2
                load_frags(frag[nb], aB, bB, 1);
                if (nk < KITERS) load_stage_A(nk, s2, m0, tid, smem_u32);
            } else if (ks == 1) {
                // prefetch frags ks2; issue B-half of stage kb+2
                load_frags(frag[nb], aB, bB, 2);
                if (nk < KITERS) load_stage_B(nk, s2, n0, tid, smem_u32);
            } else if (ks == 2) {
                // prefetch frags ks3; commit + drain + barrier
                load_frags(frag[nb], aB, bB, 3);
                cp_commit();
                cp_wait<1>();          // stage kb+1 resident
                __syncthreads();
            } else {
                // ks3: frags for next stage ks0
                if (kb + 1 < KITERS)
                    load_frags(frag[nb], stage_a(sn), stage_b(sn), 0);
            }
            #pragma unroll
            for (int mt = 0; mt < 4; mt++)
                #pragma unroll
                for (int nt = 0; nt < 8; nt++)
                    mma_f16(acc[mt][nt], frag[fb].a[mt], frag[fb].b[nt]);
            fb = nb;
        }

        s = sn;
    }

    // epilogue: streaming stores
    const int lrow_q = lane >> 2;
    const int lcol_q = lane & 3;
    const int mrow  = m0 + wm * 64 + lrow_q;
    const int ncol0 = n0 + wn * 64 + lcol_q * 2;
    #pragma unroll
    for (int mt = 0; mt < 4; mt++) {
        #pragma unroll
        for (int nt = 0; nt < 8; nt++) {
            int r = mrow + mt * 16;
            int c = ncol0 + nt * 8;
            float2 lo = make_float2(acc[mt][nt][0], acc[mt][nt][1]);
            float2 hi = make_float2(acc[mt][nt][2], acc[mt][nt][3]);
            __stcs(reinterpret_cast<float2*>(y + (size_t)r * OUT_DIM + c), lo);
            __stcs(reinterpret_cast<float2*>(y + (size_t)(r + 8) * OUT_DIM + c), hi);
        }
    }
}

extern "C" void kernel_launch(void* const* d_in, const int* in_sizes, int n_in,
                              void* d_out, int out_size) {
    const float* x      = (const float*)d_in[0];
    const float* scales = (const float*)d_in[1];
    const int*   codes  = (const int*)d_in[2];
    float*       y      = (float*)d_out;

    cudaFuncSetAttribute(gguf_hgemm12, cudaFuncAttributeMaxDynamicSharedMemorySize,
                         SMEM_BYTES);

    prepass_kernel<<<PRE_XBLK + PRE_WBLK, PRE_T>>>(
        reinterpret_cast<const float4*>(x), scales,
        reinterpret_cast<const int4*>(codes));

    dim3 grid(OUT_DIM / BN, M_DIM / BM);   // (32, 32)
    gguf_hgemm12<<<grid, THREADS, SMEM_BYTES>>>(y);
}

// round 15
// speedup vs baseline: 1.0239x; 1.0072x over previous
#include <cuda_runtime.h>
#include <cuda_fp16.h>
#include <cstdint>

// y = x @ W^T,  W[o,k] = scales[o,k/32] * (codes[o,k] - 128)
// R15 (final): R14 GEMM locked (CTA 128x128, 4 warps of 64x64, 3-stage
// cp.async, double-buffered ldmatrix frags, 2 CTA/SM, split A/B fill,
// streaming epilogue). Prepass: MLP=4, __ldcs streaming loads, x/W blocks
// interleaved for uniform DRAM read/write mix.

#define IN_DIM   4096
#define OUT_DIM  4096
#define M_DIM    4096
#define NBLK_    128

#define BM       128
#define BN       128
#define BK       64
#define STAGES   3
#define THREADS  128
#define KITERS   (IN_DIM / BK)   // 64

__device__ __half g_xh[(size_t)M_DIM * IN_DIM];
__device__ __half g_wh[(size_t)OUT_DIM * IN_DIM];

#define A_STAGE_H   (BM * BK)                     // 8192 halves (16 KB)
#define B_STAGE_H   (BN * BK)
#define B_BASE_H    (STAGES * A_STAGE_H)
#define SMEM_BYTES  ((STAGES * (A_STAGE_H + B_STAGE_H)) * 2)   // 98304

// ---------------- prepass: MLP=4, streaming loads, interleaved ----------------
#define NX4 ((M_DIM * IN_DIM) / 4)
#define NW4 ((OUT_DIM * IN_DIM) / 4)
#define PRE_T    256
#define PRE_C    4
#define PRE_XBLK (NX4 / (PRE_T * PRE_C))  // 4096
#define PRE_WBLK (NW4 / (PRE_T * PRE_C))  // 4096

__device__ __forceinline__ float4 ldcs_f4(const float4* p) {
    float4 v;
    asm volatile("ld.global.cs.v4.f32 {%0,%1,%2,%3}, [%4];"
                 : "=f"(v.x), "=f"(v.y), "=f"(v.z), "=f"(v.w) : "l"(p));
    return v;
}
__device__ __forceinline__ int4 ldcs_i4(const int4* p) {
    int4 v;
    asm volatile("ld.global.cs.v4.s32 {%0,%1,%2,%3}, [%4];"
                 : "=r"(v.x), "=r"(v.y), "=r"(v.z), "=r"(v.w) : "l"(p));
    return v;
}

__global__ void prepass_kernel(const float4* __restrict__ x,
                               const float* __restrict__ scales,
                               const int4* __restrict__ codes) {
    int b = blockIdx.x;
    // interleave: even blocks -> x conversion, odd blocks -> W dequant
    if ((b & 1) == 0) {
        int xb = b >> 1;                       // 0..PRE_XBLK-1
        int base = xb * (PRE_T * PRE_C) + threadIdx.x;
        float4 v[PRE_C];
        #pragma unroll
        for (int j = 0; j < PRE_C; j++) v[j] = ldcs_f4(x + base + j * PRE_T);
        #pragma unroll
        for (int j = 0; j < PRE_C; j++) {
            __half2 h0 = __floats2half2_rn(v[j].x, v[j].y);
            __half2 h1 = __floats2half2_rn(v[j].z, v[j].w);
            uint2 u;
            u.x = *reinterpret_cast<uint32_t*>(&h0);
            u.y = *reinterpret_cast<uint32_t*>(&h1);
            reinterpret_cast<uint2*>(g_xh)[base + j * PRE_T] = u;
        }
    } else {
        int wb = b >> 1;                       // 0..PRE_WBLK-1
        int base = wb * (PRE_T * PRE_C) + threadIdx.x;
        int4 c[PRE_C];
        float s[PRE_C];
        #pragma unroll
        for (int j = 0; j < PRE_C; j++) {
            int idx = base + j * PRE_T;
            c[j] = ldcs_i4(codes + idx);
            int gelt = idx * 4;
            s[j] = __ldg(scales + (gelt >> 12) * NBLK_ + ((gelt & 4095) >> 5));
        }
        #pragma unroll
        for (int j = 0; j < PRE_C; j++) {
            __half2 h0 = __floats2half2_rn(s[j] * (float)(c[j].x - 128),
                                           s[j] * (float)(c[j].y - 128));
            __half2 h1 = __floats2half2_rn(s[j] * (float)(c[j].z - 128),
                                           s[j] * (float)(c[j].w - 128));
            uint2 u;
            u.x = *reinterpret_cast<uint32_t*>(&h0);
            u.y = *reinterpret_cast<uint32_t*>(&h1);
            reinterpret_cast<uint2*>(g_wh)[base + j * PRE_T] = u;
        }
    }
}

// ---------------- GEMM helpers ----------------

__device__ __forceinline__ void cp_async16(uint32_t saddr, const void* g) {
    asm volatile("cp.async.cg.shared.global [%0], [%1], 16;" :: "r"(saddr), "l"(g));
}
__device__ __forceinline__ void cp_commit() {
    asm volatile("cp.async.commit_group;");
}
template <int N>
__device__ __forceinline__ void cp_wait() {
    asm volatile("cp.async.wait_group %0;" :: "n"(N));
}
__device__ __forceinline__ void ldsm_x4(uint32_t& r0, uint32_t& r1,
                                        uint32_t& r2, uint32_t& r3, uint32_t addr) {
    asm volatile("ldmatrix.sync.aligned.m8n8.x4.shared.b16 {%0,%1,%2,%3}, [%4];"
                 : "=r"(r0), "=r"(r1), "=r"(r2), "=r"(r3) : "r"(addr));
}
__device__ __forceinline__ void mma_f16(float* c, const uint32_t* a, const uint32_t* b) {
    asm volatile(
        "mma.sync.aligned.m16n8k16.row.col.f32.f16.f16.f32 "
        "{%0,%1,%2,%3}, {%4,%5,%6,%7}, {%8,%9}, {%0,%1,%2,%3};"
        : "+f"(c[0]), "+f"(c[1]), "+f"(c[2]), "+f"(c[3])
        : "r"(a[0]), "r"(a[1]), "r"(a[2]), "r"(a[3]), "r"(b[0]), "r"(b[1]));
}

__device__ __forceinline__ int tile_off(int row, int chunk) {
    return row * BK + ((chunk ^ (row & 7)) << 3);
}

__device__ __forceinline__ void load_stage_A(int kb, int st, int m0,
                                             int tid, uint32_t smem_u32) {
    const __half* gA = g_xh + (size_t)m0 * IN_DIM + kb * BK;
    uint32_t aBase = smem_u32 + (uint32_t)(st * A_STAGE_H) * 2;
    #pragma unroll
    for (int it = 0; it < 8; it++) {
        int idx = tid + it * THREADS;
        int row = idx >> 3, ch = idx & 7;
        cp_async16(aBase + (uint32_t)tile_off(row, ch) * 2,
                   gA + (size_t)row * IN_DIM + ch * 8);
    }
}
__device__ __forceinline__ void load_stage_B(int kb, int st, int n0,
                                             int tid, uint32_t smem_u32) {
    const __half* gB = g_wh + (size_t)n0 * IN_DIM + kb * BK;
    uint32_t bBase = smem_u32 + (uint32_t)(B_BASE_H + st * B_STAGE_H) * 2;
    #pragma unroll
    for (int it = 0; it < 8; it++) {
        int idx = tid + it * THREADS;
        int row = idx >> 3, ch = idx & 7;
        cp_async16(bBase + (uint32_t)tile_off(row, ch) * 2,
                   gB + (size_t)row * IN_DIM + ch * 8);
    }
}

struct Frag {
    uint32_t a[4][4];
    uint32_t b[8][2];
};

__global__ __launch_bounds__(THREADS, 2)
void gguf_hgemm13(float* __restrict__ y) {
    extern __shared__ __half sm[];
    uint32_t smem_u32 = (uint32_t)__cvta_generic_to_shared(sm);

    const int tid  = threadIdx.x;
    const int lane = tid & 31;
    const int wid  = tid >> 5;
    const int wm   = wid >> 1;     // 0..1 -> 64 m rows
    const int wn   = wid & 1;      // 0..1 -> 64 n cols

    const int m0 = blockIdx.y * BM;
    const int n0 = blockIdx.x * BN;

    float acc[4][8][4];
    #pragma unroll
    for (int i = 0; i < 4; i++)
        #pragma unroll
        for (int j = 0; j < 8; j++)
            #pragma unroll
            for (int v = 0; v < 4; v++) acc[i][j][v] = 0.0f;

    const int a_lr = lane & 15;
    const int a_lc = lane >> 4;
    const int b_lr = (lane & 7) + ((lane >> 4) << 3);
    const int b_lc = (lane >> 3) & 1;

    int rowA[4], rowB[4];
    #pragma unroll
    for (int mt = 0; mt < 4; mt++) rowA[mt] = wm * 64 + mt * 16 + a_lr;
    #pragma unroll
    for (int p = 0; p < 4; p++)    rowB[p]  = wn * 64 + p * 16 + b_lr;

    auto load_frags = [&](Frag& f, uint32_t aBase, uint32_t bBase, int ks) {
        const int ck0 = ks * 2;
        #pragma unroll
        for (int mt = 0; mt < 4; mt++) {
            int r = rowA[mt];
            uint32_t addr = aBase +
                (uint32_t)(r * BK + (((ck0 + a_lc) ^ (r & 7)) << 3)) * 2;
            ldsm_x4(f.a[mt][0], f.a[mt][1], f.a[mt][2], f.a[mt][3], addr);
        }
        #pragma unroll
        for (int p = 0; p < 4; p++) {
            int r = rowB[p];
            uint32_t addr = bBase +
                (uint32_t)(r * BK + (((ck0 + b_lc) ^ (r & 7)) << 3)) * 2;
            uint32_t r0, r1, r2, r3;
            ldsm_x4(r0, r1, r2, r3, addr);
            f.b[2 * p][0] = r0;     f.b[2 * p][1] = r1;
            f.b[2 * p + 1][0] = r2; f.b[2 * p + 1][1] = r3;
        }
    };

    auto stage_a = [&](int s) {
        return smem_u32 + (uint32_t)(s * A_STAGE_H) * 2;
    };
    auto stage_b = [&](int s) {
        return smem_u32 + (uint32_t)(B_BASE_H + s * B_STAGE_H) * 2;
    };

    // prologue
    load_stage_A(0, 0, m0, tid, smem_u32);
    load_stage_B(0, 0, n0, tid, smem_u32); cp_commit();
    load_stage_A(1, 1, m0, tid, smem_u32);
    load_stage_B(1, 1, n0, tid, smem_u32); cp_commit();
    cp_wait<1>();
    __syncthreads();

    Frag frag[2];
    load_frags(frag[0], stage_a(0), stage_b(0), 0);
    int fb = 0;

    int s = 0;
    for (int kb = 0; kb < KITERS; kb++) {
        const uint32_t aB = stage_a(s);
        const uint32_t bB = stage_b(s);
        const int sn = (s + 1 == STAGES) ? 0 : s + 1;
        const int nk = kb + 2;
        const int s2 = (s + 2 >= STAGES) ? s + 2 - STAGES : s + 2;

        #pragma unroll
        for (int ks = 0; ks < BK / 16; ks++) {
            const int nb = fb ^ 1;
            if (ks == 0) {
                load_frags(frag[nb], aB, bB, 1);
                if (nk < KITERS) load_stage_A(nk, s2, m0, tid, smem_u32);
            } else if (ks == 1) {
                load_frags(frag[nb], aB, bB, 2);
                if (nk < KITERS) load_stage_B(nk, s2, n0, tid, smem_u32);
            } else if (ks == 2) {
                load_frags(frag[nb], aB, bB, 3);
                cp_commit();
                cp_wait<1>();          // stage kb+1 resident
                __syncthreads();
            } else {
                if (kb + 1 < KITERS)
                    load_frags(frag[nb], stage_a(sn), stage_b(sn), 0);
            }
            #pragma unroll
            for (int mt = 0; mt < 4; mt++)
                #pragma unroll
                for (int nt = 0; nt < 8; nt++)
                    mma_f16(acc[mt][nt], frag[fb].a[mt], frag[fb].b[nt]);
            fb = nb;
        }

        s = sn;
    }

    // epilogue: streaming stores
    const int lrow_q = lane >> 2;
    const int lcol_q = lane & 3;
    const int mrow  = m0 + wm * 64 + lrow_q;
    const int ncol0 = n0 + wn * 64 + lcol_q * 2;
    #pragma unroll
    for (int mt = 0; mt < 4; mt++) {
        #pragma unroll
        for (int nt = 0; nt < 8; nt++) {
            int r = mrow + mt * 16;
            int c = ncol0 + nt * 8;
            float2 lo = make_float2(acc[mt][nt][0], acc[mt][nt][1]);
            float2 hi = make_float2(acc[mt][nt][2], acc[mt][nt][3]);
            __stcs(reinterpret_cast<float2*>(y + (size_t)r * OUT_DIM + c), lo);
            __stcs(reinterpret_cast<float2*>(y + (size_t)(r + 8) * OUT_DIM + c), hi);
        }
    }
}

extern "C" void kernel_launch(void* const* d_in, const int* in_sizes, int n_in,
                              void* d_out, int out_size) {
    const float* x      = (const float*)d_in[0];
    const float* scales = (const float*)d_in[1];
    const int*   codes  = (const int*)d_in[2];
    float*       y      = (float*)d_out;

    cudaFuncSetAttribute(gguf_hgemm13, cudaFuncAttributeMaxDynamicSharedMemorySize,
                         SMEM_BYTES);

    prepass_kernel<<<PRE_XBLK + PRE_WBLK, PRE_T>>>(
        reinterpret_cast<const float4*>(x), scales,
        reinterpret_cast<const int4*>(codes));

    dim3 grid(OUT_DIM / BN, M_DIM / BM);   // (32, 32)
    gguf_hgemm13<<<grid, THREADS, SMEM_BYTES>>>(y);
}

// round 16
// speedup vs baseline: 1.0303x; 1.0062x over previous
#include <cuda_runtime.h>
#include <cuda_fp16.h>
#include <cstdint>

// y = x @ W^T,  W[o,k] = scales[o,k/32] * (codes[o,k] - 128)
// R16: R15 kernels unchanged (prepass MLP=4/__ldcs/interleaved; GEMM CTA
// 128x128, 4 warps of 64x64, 3-stage cp.async, double-buffered ldmatrix
// frags, 2 CTA/SM, split A/B fill, streaming epilogue) + programmatic
// dependent launch: GEMM launches early, CTAs wait on griddepcontrol
// before first reads -> overlaps launch gap/ramp with prepass tail.

#define IN_DIM   4096
#define OUT_DIM  4096
#define M_DIM    4096
#define NBLK_    128

#define BM       128
#define BN       128
#define BK       64
#define STAGES   3
#define THREADS  128
#define KITERS   (IN_DIM / BK)   // 64

__device__ __half g_xh[(size_t)M_DIM * IN_DIM];
__device__ __half g_wh[(size_t)OUT_DIM * IN_DIM];

#define A_STAGE_H   (BM * BK)                     // 8192 halves (16 KB)
#define B_STAGE_H   (BN * BK)
#define B_BASE_H    (STAGES * A_STAGE_H)
#define SMEM_BYTES  ((STAGES * (A_STAGE_H + B_STAGE_H)) * 2)   // 98304

// ---------------- prepass ----------------
#define NX4 ((M_DIM * IN_DIM) / 4)
#define NW4 ((OUT_DIM * IN_DIM) / 4)
#define PRE_T    256
#define PRE_C    4
#define PRE_XBLK (NX4 / (PRE_T * PRE_C))  // 4096
#define PRE_WBLK (NW4 / (PRE_T * PRE_C))  // 4096

__device__ __forceinline__ float4 ldcs_f4(const float4* p) {
    float4 v;
    asm volatile("ld.global.cs.v4.f32 {%0,%1,%2,%3}, [%4];"
                 : "=f"(v.x), "=f"(v.y), "=f"(v.z), "=f"(v.w) : "l"(p));
    return v;
}
__device__ __forceinline__ int4 ldcs_i4(const int4* p) {
    int4 v;
    asm volatile("ld.global.cs.v4.s32 {%0,%1,%2,%3}, [%4];"
                 : "=r"(v.x), "=r"(v.y), "=r"(v.z), "=r"(v.w) : "l"(p));
    return v;
}

__global__ void prepass_kernel(const float4* __restrict__ x,
                               const float* __restrict__ scales,
                               const int4* __restrict__ codes) {
    int b = blockIdx.x;
    if ((b & 1) == 0) {
        int xb = b >> 1;
        int base = xb * (PRE_T * PRE_C) + threadIdx.x;
        float4 v[PRE_C];
        #pragma unroll
        for (int j = 0; j < PRE_C; j++) v[j] = ldcs_f4(x + base + j * PRE_T);
        #pragma unroll
        for (int j = 0; j < PRE_C; j++) {
            __half2 h0 = __floats2half2_rn(v[j].x, v[j].y);
            __half2 h1 = __floats2half2_rn(v[j].z, v[j].w);
            uint2 u;
            u.x = *reinterpret_cast<uint32_t*>(&h0);
            u.y = *reinterpret_cast<uint32_t*>(&h1);
            reinterpret_cast<uint2*>(g_xh)[base + j * PRE_T] = u;
        }
    } else {
        int wb = b >> 1;
        int base = wb * (PRE_T * PRE_C) + threadIdx.x;
        int4 c[PRE_C];
        float s[PRE_C];
        #pragma unroll
        for (int j = 0; j < PRE_C; j++) {
            int idx = base + j * PRE_T;
            c[j] = ldcs_i4(codes + idx);
            int gelt = idx * 4;
            s[j] = __ldg(scales + (gelt >> 12) * NBLK_ + ((gelt & 4095) >> 5));
        }
        #pragma unroll
        for (int j = 0; j < PRE_C; j++) {
            __half2 h0 = __floats2half2_rn(s[j] * (float)(c[j].x - 128),
                                           s[j] * (float)(c[j].y - 128));
            __half2 h1 = __floats2half2_rn(s[j] * (float)(c[j].z - 128),
                                           s[j] * (float)(c[j].w - 128));
            uint2 u;
            u.x = *reinterpret_cast<uint32_t*>(&h0);
            u.y = *reinterpret_cast<uint32_t*>(&h1);
            reinterpret_cast<uint2*>(g_wh)[base + j * PRE_T] = u;
        }
    }
    // allow the dependent GEMM grid to begin launching/scheduling
    cudaTriggerProgrammaticLaunchCompletion();
}

// ---------------- GEMM helpers ----------------

__device__ __forceinline__ void cp_async16(uint32_t saddr, const void* g) {
    asm volatile("cp.async.cg.shared.global [%0], [%1], 16;" :: "r"(saddr), "l"(g));
}
__device__ __forceinline__ void cp_commit() {
    asm volatile("cp.async.commit_group;");
}
template <int N>
__device__ __forceinline__ void cp_wait() {
    asm volatile("cp.async.wait_group %0;" :: "n"(N));
}
__device__ __forceinline__ void ldsm_x4(uint32_t& r0, uint32_t& r1,
                                        uint32_t& r2, uint32_t& r3, uint32_t addr) {
    asm volatile("ldmatrix.sync.aligned.m8n8.x4.shared.b16 {%0,%1,%2,%3}, [%4];"
                 : "=r"(r0), "=r"(r1), "=r"(r2), "=r"(r3) : "r"(addr));
}
__device__ __forceinline__ void mma_f16(float* c, const uint32_t* a, const uint32_t* b) {
    asm volatile(
        "mma.sync.aligned.m16n8k16.row.col.f32.f16.f16.f32 "
        "{%0,%1,%2,%3}, {%4,%5,%6,%7}, {%8,%9}, {%0,%1,%2,%3};"
        : "+f"(c[0]), "+f"(c[1]), "+f"(c[2]), "+f"(c[3])
        : "r"(a[0]), "r"(a[1]), "r"(a[2]), "r"(a[3]), "r"(b[0]), "r"(b[1]));
}

__device__ __forceinline__ int tile_off(int row, int chunk) {
    return row * BK + ((chunk ^ (row & 7)) << 3);
}

__device__ __forceinline__ void load_stage_A(int kb, int st, int m0,
                                             int tid, uint32_t smem_u32) {
    const __half* gA = g_xh + (size_t)m0 * IN_DIM + kb * BK;
    uint32_t aBase = smem_u32 + (uint32_t)(st * A_STAGE_H) * 2;
    #pragma unroll
    for (int it = 0; it < 8; it++) {
        int idx = tid + it * THREADS;
        int row = idx >> 3, ch = idx & 7;
        cp_async16(aBase + (uint32_t)tile_off(row, ch) * 2,
                   gA + (size_t)row * IN_DIM + ch * 8);
    }
}
__device__ __forceinline__ void load_stage_B(int kb, int st, int n0,
                                             int tid, uint32_t smem_u32) {
    const __half* gB = g_wh + (size_t)n0 * IN_DIM + kb * BK;
    uint32_t bBase = smem_u32 + (uint32_t)(B_BASE_H + st * B_STAGE_H) * 2;
    #pragma unroll
    for (int it = 0; it < 8; it++) {
        int idx = tid + it * THREADS;
        int row = idx >> 3, ch = idx & 7;
        cp_async16(bBase + (uint32_t)tile_off(row, ch) * 2,
                   gB + (size_t)row * IN_DIM + ch * 8);
    }
}

struct Frag {
    uint32_t a[4][4];
    uint32_t b[8][2];
};

__global__ __launch_bounds__(THREADS, 2)
void gguf_hgemm14(float* __restrict__ y) {
    extern __shared__ __half sm[];
    uint32_t smem_u32 = (uint32_t)__cvta_generic_to_shared(sm);

    const int tid  = threadIdx.x;
    const int lane = tid & 31;
    const int wid  = tid >> 5;
    const int wm   = wid >> 1;     // 0..1 -> 64 m rows
    const int wn   = wid & 1;      // 0..1 -> 64 n cols

    const int m0 = blockIdx.y * BM;
    const int n0 = blockIdx.x * BN;

    float acc[4][8][4];
    #pragma unroll
    for (int i = 0; i < 4; i++)
        #pragma unroll
        for (int j = 0; j < 8; j++)
            #pragma unroll
            for (int v = 0; v < 4; v++) acc[i][j][v] = 0.0f;

    const int a_lr = lane & 15;
    const int a_lc = lane >> 4;
    const int b_lr = (lane & 7) + ((lane >> 4) << 3);
    const int b_lc = (lane >> 3) & 1;

    int rowA[4], rowB[4];
    #pragma unroll
    for (int mt = 0; mt < 4; mt++) rowA[mt] = wm * 64 + mt * 16 + a_lr;
    #pragma unroll
    for (int p = 0; p < 4; p++)    rowB[p]  = wn * 64 + p * 16 + b_lr;

    // wait for the prepass grid's memory to be visible before first reads
    cudaGridDependencySynchronize();

    auto load_frags = [&](Frag& f, uint32_t aBase, uint32_t bBase, int ks) {
        const int ck0 = ks * 2;
        #pragma unroll
        for (int mt = 0; mt < 4; mt++) {
            int r = rowA[mt];
            uint32_t addr = aBase +
                (uint32_t)(r * BK + (((ck0 + a_lc) ^ (r & 7)) << 3)) * 2;
            ldsm_x4(f.a[mt][0], f.a[mt][1], f.a[mt][2], f.a[mt][3], addr);
        }
        #pragma unroll
        for (int p = 0; p < 4; p++) {
            int r = rowB[p];
            uint32_t addr = bBase +
                (uint32_t)(r * BK + (((ck0 + b_lc) ^ (r & 7)) << 3)) * 2;
            uint32_t r0, r1, r2, r3;
            ldsm_x4(r0, r1, r2, r3, addr);
            f.b[2 * p][0] = r0;     f.b[2 * p][1] = r1;
            f.b[2 * p + 1][0] = r2; f.b[2 * p + 1][1] = r3;
        }
    };

    auto stage_a = [&](int s) {
        return smem_u32 + (uint32_t)(s * A_STAGE_H) * 2;
    };
    auto stage_b = [&](int s) {
        return smem_u32 + (uint32_t)(B_BASE_H + s * B_STAGE_H) * 2;
    };

    // prologue
    load_stage_A(0, 0, m0, tid, smem_u32);
    load_stage_B(0, 0, n0, tid, smem_u32); cp_commit();
    load_stage_A(1, 1, m0, tid, smem_u32);
    load_stage_B(1, 1, n0, tid, smem_u32); cp_commit();
    cp_wait<1>();
    __syncthreads();

    Frag frag[2];
    load_frags(frag[0], stage_a(0), stage_b(0), 0);
    int fb = 0;

    int s = 0;
    for (int kb = 0; kb < KITERS; kb++) {
        const uint32_t aB = stage_a(s);
        const uint32_t bB = stage_b(s);
        const int sn = (s + 1 == STAGES) ? 0 : s + 1;
        const int nk = kb + 2;
        const int s2 = (s + 2 >= STAGES) ? s + 2 - STAGES : s + 2;

        #pragma unroll
        for (int ks = 0; ks < BK / 16; ks++) {
            const int nb = fb ^ 1;
            if (ks == 0) {
                load_frags(frag[nb], aB, bB, 1);
                if (nk < KITERS) load_stage_A(nk, s2, m0, tid, smem_u32);
            } else if (ks == 1) {
                load_frags(frag[nb], aB, bB, 2);
                if (nk < KITERS) load_stage_B(nk, s2, n0, tid, smem_u32);
            } else if (ks == 2) {
                load_frags(frag[nb], aB, bB, 3);
                cp_commit();
                cp_wait<1>();          // stage kb+1 resident
                __syncthreads();
            } else {
                if (kb + 1 < KITERS)
                    load_frags(frag[nb], stage_a(sn), stage_b(sn), 0);
            }
            #pragma unroll
            for (int mt = 0; mt < 4; mt++)
                #pragma unroll
                for (int nt = 0; nt < 8; nt++)
                    mma_f16(acc[mt][nt], frag[fb].a[mt], frag[fb].b[nt]);
            fb = nb;
        }

        s = sn;
    }

    // epilogue: streaming stores
    const int lrow_q = lane >> 2;
    const int lcol_q = lane & 3;
    const int mrow  = m0 + wm * 64 + lrow_q;
    const int ncol0 = n0 + wn * 64 + lcol_q * 2;
    #pragma unroll
    for (int mt = 0; mt < 4; mt++) {
        #pragma unroll
        for (int nt = 0; nt < 8; nt++) {
            int r = mrow + mt * 16;
            int c = ncol0 + nt * 8;
            float2 lo = make_float2(acc[mt][nt][0], acc[mt][nt][1]);
            float2 hi = make_float2(acc[mt][nt][2], acc[mt][nt][3]);
            __stcs(reinterpret_cast<float2*>(y + (size_t)r * OUT_DIM + c), lo);
            __stcs(reinterpret_cast<float2*>(y + (size_t)(r + 8) * OUT_DIM + c), hi);
        }
    }
}

extern "C" void kernel_launch(void* const* d_in, const int* in_sizes, int n_in,
                              void* d_out, int out_size) {
    const float* x      = (const float*)d_in[0];
    const float* scales = (const float*)d_in[1];
    const int*   codes  = (const int*)d_in[2];
    float*       y      = (float*)d_out;

    cudaFuncSetAttribute(gguf_hgemm14, cudaFuncAttributeMaxDynamicSharedMemorySize,
                         SMEM_BYTES);

    prepass_kernel<<<PRE_XBLK + PRE_WBLK, PRE_T>>>(
        reinterpret_cast<const float4*>(x), scales,
        reinterpret_cast<const int4*>(codes));

    // GEMM with programmatic dependent launch: overlaps launch/ramp with
    // the prepass tail; data dependency enforced in-kernel.
    cudaLaunchConfig_t cfg = {};
    cfg.gridDim = dim3(OUT_DIM / BN, M_DIM / BM, 1);   // (32, 32)
    cfg.blockDim = dim3(THREADS, 1, 1);
    cfg.dynamicSmemBytes = SMEM_BYTES;
    cfg.stream = 0;
    cudaLaunchAttribute attr[1];
    attr[0].id = cudaLaunchAttributeProgrammaticStreamSerialization;
    attr[0].val.programmaticStreamSerializationAllowed = 1;
    cfg.attrs = attr;
    cfg.numAttrs = 1;
    cudaError_t err = cudaLaunchKernelEx(&cfg, gguf_hgemm14, y);
    if (err != cudaSuccess) {
        // fallback: plain launch (still correct, just serialized)
        gguf_hgemm14<<<dim3(OUT_DIM / BN, M_DIM / BM), THREADS, SMEM_BYTES>>>(y);
    }
}